// round 9
// baseline (speedup 1.0000x reference)
#include <cuda_runtime.h>
#include <cuda_fp16.h>
#include <cstdint>

// ---------------- problem constants (fixed by reference_code) ----------------
#define N_USERS 100000
#define N_ITEMS 50000
#define N_NODES 150000          // N_USERS + N_ITEMS
#define KPU 32                  // items per user
#define E_UI  (N_USERS * KPU)   // 3,200,000 user->item edges (first block)
#define SELF_BASE (2 * E_UI)    // self-loop edges start at 6,400,000
#define D 64                    // embed dim (all layers)
#define OD 256                  // output row width: 64 + 3*64
#define MAXDEG 128              // padded item adjacency slots

// ---------------- device scratch (no allocation allowed) ----------------
__device__ int    g_fill[N_ITEMS];
__device__ int    g_adj2[(size_t)N_ITEMS * MAXDEG];     // 25.6 MB item->user lists
__device__ __half g_ph[2][(size_t)N_NODES * D];         // 2x 19.2 MB fp16 ping-pong

// ---------------- CSR build: 2 kernels (padded slots, no scan) --------------
__global__ void zero_fill_kernel() {
    int i = blockIdx.x * blockDim.x + threadIdx.x;
    if (i < N_ITEMS) g_fill[i] = 0;
}

__global__ void fill2_kernel(const int* __restrict__ cols) {
    int e = blockIdx.x * blockDim.x + threadIdx.x;
    if (e >= E_UI) return;
    int item = cols[e] - N_USERS;
    int pos  = atomicAdd(&g_fill[item], 1);
    if (pos < MAXDEG) g_adj2[item * MAXDEG + pos] = e >> 5;  // user = edge/32
}

// ---------------- ego copy: out[:,0:64] = concat(ue, ie); fp16 pack to buf 0 -
__global__ void ego_copy_kernel(const float* __restrict__ ue,
                                const float* __restrict__ ie,
                                float* __restrict__ out) {
    int idx = blockIdx.x * blockDim.x + threadIdx.x;   // one float4 each
    if (idx >= N_NODES * (D / 4)) return;
    int n  = idx >> 4;
    int c4 = idx & 15;
    float4 v = (n < N_USERS)
        ? reinterpret_cast<const float4*>(ue)[(size_t)n * (D/4) + c4]
        : reinterpret_cast<const float4*>(ie)[(size_t)(n - N_USERS) * (D/4) + c4];
    reinterpret_cast<float4*>(out)[(size_t)n * (OD/4) + c4] = v;
    __half2 h0 = __floats2half2_rn(v.x, v.y);
    __half2 h1 = __floats2half2_rn(v.z, v.w);
    reinterpret_cast<uint2*>(g_ph[0])[(size_t)n * (D/4) + c4] =
        make_uint2(*reinterpret_cast<unsigned*>(&h0), *reinterpret_cast<unsigned*>(&h1));
}

// 8-deep fp16 gather batch: 8 independent LDG.64 in flight (1 line per row).
__device__ __forceinline__ void gather8h(const __half* __restrict__ ph,
                                         unsigned hmask, int src, int base,
                                         int hl, float4& acc) {
    uint2 v[8];
    #pragma unroll
    for (int j = 0; j < 8; j++) {
        int c = __shfl_sync(hmask, src, base + j, 16);
        v[j] = reinterpret_cast<const uint2*>(ph + (size_t)c * D)[hl];
    }
    float4 t0 = make_float4(0.f,0.f,0.f,0.f);
    float4 t1 = make_float4(0.f,0.f,0.f,0.f);
    #pragma unroll
    for (int j = 0; j < 8; j += 2) {
        float2 a0 = __half22float2(*reinterpret_cast<__half2*>(&v[j].x));
        float2 b0 = __half22float2(*reinterpret_cast<__half2*>(&v[j].y));
        float2 a1 = __half22float2(*reinterpret_cast<__half2*>(&v[j+1].x));
        float2 b1 = __half22float2(*reinterpret_cast<__half2*>(&v[j+1].y));
        t0.x += a0.x; t0.y += a0.y; t0.z += b0.x; t0.w += b0.y;
        t1.x += a1.x; t1.y += a1.y; t1.z += b1.x; t1.w += b1.y;
    }
    acc.x += t0.x + t1.x; acc.y += t0.y + t1.y;
    acc.z += t0.z + t1.z; acc.w += t0.w + t1.w;
}

// ---------------- fused layer: gather + dual GEMM + lrelu + L2-norm ---------
// Half-warp per 4-node group; grid-stride; weights loaded once per block.
// Gathers come from packed fp16 buffer (128B rows); self row read fp32.
__global__ void __launch_bounds__(256, 4)
fused_layer_kernel(const int* __restrict__ cols,
                   const float* __restrict__ vals,
                   const float* __restrict__ prevc,    // fp32, stride OD (self row)
                   float* __restrict__ outc,           // fp32, stride OD
                   const float* __restrict__ Ws, const float* __restrict__ bs,
                   const float* __restrict__ Wp, const float* __restrict__ bp,
                   int srcbuf, int ngroups) {
    __shared__ float sWs[D * D];            // 16 KB
    __shared__ float sWp[D * D];            // 16 KB
    __shared__ uint2 sS[16][4][16];         // 8 KB
    __shared__ uint2 sP[16][4][16];         // 8 KB -> 48 KB total

    const __half* ph  = g_ph[srcbuf];
    __half*       phd = g_ph[srcbuf ^ 1];

    int tx = threadIdx.x;
    for (int i = tx; i < D * D; i += 256) { sWs[i] = Ws[i]; sWp[i] = Wp[i]; }

    int h  = tx >> 4;
    int hl = tx & 15;
    unsigned hmask = 0xFFFFu << (tx & 16);

    float4 breg;
    breg.x = bs[hl*4+0] + bp[hl*4+0];
    breg.y = bs[hl*4+1] + bp[hl*4+1];
    breg.z = bs[hl*4+2] + bp[hl*4+2];
    breg.w = bs[hl*4+3] + bp[hl*4+3];
    __syncthreads();

    for (int grp = blockIdx.x; grp < ngroups; grp += gridDim.x) {
        int nodeBase = (grp * 16 + h) * 4;

        // ---------------- Phase A: gather 4 nodes ----------------
        #pragma unroll
        for (int i = 0; i < 4; i++) {
            int n = nodeBase + i;
            if (n >= N_NODES) {
                sS[h][i][hl] = make_uint2(0u, 0u);
                sP[h][i][hl] = make_uint2(0u, 0u);
                continue;
            }
            float4 pself = reinterpret_cast<const float4*>(prevc + (size_t)n * OD)[hl];
            float4 acc = pself;    // self term exact fp32
            if (n < N_USERS) {
                const int* cu = cols + n * KPU;
                int c_lo = cu[hl];
                int c_hi = cu[16 + hl];
                gather8h(ph, hmask, c_lo, 0, hl, acc);
                gather8h(ph, hmask, c_lo, 8, hl, acc);
                gather8h(ph, hmask, c_hi, 0, hl, acc);
                gather8h(ph, hmask, c_hi, 8, hl, acc);
            } else {
                int it  = n - N_USERS;
                int cnt = g_fill[it]; if (cnt > MAXDEG) cnt = MAXDEG;
                const int* adj = g_adj2 + (size_t)it * MAXDEG;
                int p = 0;
                for (; p + 16 <= cnt; p += 16) {
                    int myu = adj[p + hl];
                    gather8h(ph, hmask, myu, 0, hl, acc);
                    gather8h(ph, hmask, myu, 8, hl, acc);
                }
                int rem = cnt - p;
                if (rem > 0) {
                    int myu = (hl < rem) ? adj[p + hl] : 0;
                    for (int j = 0; j < rem; j++) {
                        int uu = __shfl_sync(hmask, myu, j, 16);
                        uint2 u = reinterpret_cast<const uint2*>(ph + (size_t)uu * D)[hl];
                        float2 a = __half22float2(*reinterpret_cast<__half2*>(&u.x));
                        float2 b = __half22float2(*reinterpret_cast<__half2*>(&u.y));
                        acc.x += a.x; acc.y += a.y; acc.z += b.x; acc.w += b.y;
                    }
                }
            }
            float sv = vals[SELF_BASE + n];   // 1/deg[n]
            float4 sd = make_float4(acc.x*sv, acc.y*sv, acc.z*sv, acc.w*sv);
            float4 pp = make_float4(sd.x*pself.x, sd.y*pself.y, sd.z*pself.z, sd.w*pself.w);
            __half2 s0 = __floats2half2_rn(sd.x, sd.y);
            __half2 s1 = __floats2half2_rn(sd.z, sd.w);
            __half2 p0 = __floats2half2_rn(pp.x, pp.y);
            __half2 p1 = __floats2half2_rn(pp.z, pp.w);
            sS[h][i][hl] = make_uint2(*reinterpret_cast<unsigned*>(&s0),
                                      *reinterpret_cast<unsigned*>(&s1));
            sP[h][i][hl] = make_uint2(*reinterpret_cast<unsigned*>(&p0),
                                      *reinterpret_cast<unsigned*>(&p1));
        }
        __syncwarp();

        // ---------------- Phase B: dual GEMM out of smem ----------------
        float accd[4][4];
        #pragma unroll
        for (int i = 0; i < 4; i++) {
            accd[i][0] = breg.x; accd[i][1] = breg.y;
            accd[i][2] = breg.z; accd[i][3] = breg.w;
        }

        #pragma unroll
        for (int j4 = 0; j4 < 16; j4++) {
            float4 vS[4], vP[4];
            #pragma unroll
            for (int i = 0; i < 4; i++) {
                uint2 uS = sS[h][i][j4];
                uint2 uP = sP[h][i][j4];
                float2 a = __half22float2(*reinterpret_cast<__half2*>(&uS.x));
                float2 b = __half22float2(*reinterpret_cast<__half2*>(&uS.y));
                vS[i] = make_float4(a.x, a.y, b.x, b.y);
                float2 c = __half22float2(*reinterpret_cast<__half2*>(&uP.x));
                float2 d = __half22float2(*reinterpret_cast<__half2*>(&uP.y));
                vP[i] = make_float4(c.x, c.y, d.x, d.y);
            }
            #pragma unroll
            for (int jj = 0; jj < 4; jj++) {
                int j = j4 * 4 + jj;
                float4 w1 = *reinterpret_cast<const float4*>(sWs + j * D + hl * 4);
                float4 w2 = *reinterpret_cast<const float4*>(sWp + j * D + hl * 4);
                #pragma unroll
                for (int i = 0; i < 4; i++) {
                    float s  = (jj == 0) ? vS[i].x : (jj == 1) ? vS[i].y
                             : (jj == 2) ? vS[i].z : vS[i].w;
                    float sp = (jj == 0) ? vP[i].x : (jj == 1) ? vP[i].y
                             : (jj == 2) ? vP[i].z : vP[i].w;
                    accd[i][0] += s * w1.x + sp * w2.x;
                    accd[i][1] += s * w1.y + sp * w2.y;
                    accd[i][2] += s * w1.z + sp * w2.z;
                    accd[i][3] += s * w1.w + sp * w2.w;
                }
            }
        }

        // ---------------- epilogue: lrelu + L2 norm + stores ----------------
        #pragma unroll
        for (int i = 0; i < 4; i++) {
            float sq = 0.0f;
            #pragma unroll
            for (int c = 0; c < 4; c++) {
                float v = accd[i][c];
                v = (v >= 0.0f) ? v : 0.2f * v;
                accd[i][c] = v;
                sq += v * v;
            }
            sq += __shfl_xor_sync(hmask, sq, 1, 16);
            sq += __shfl_xor_sync(hmask, sq, 2, 16);
            sq += __shfl_xor_sync(hmask, sq, 4, 16);
            sq += __shfl_xor_sync(hmask, sq, 8, 16);
            float inv = 1.0f / fmaxf(sqrtf(sq), 1e-12f);
            int n = nodeBase + i;
            if (n < N_NODES) {
                float4 o = make_float4(accd[i][0]*inv, accd[i][1]*inv,
                                       accd[i][2]*inv, accd[i][3]*inv);
                reinterpret_cast<float4*>(outc + (size_t)n * OD)[hl] = o;
                __half2 h0 = __floats2half2_rn(o.x, o.y);
                __half2 h1 = __floats2half2_rn(o.z, o.w);
                reinterpret_cast<uint2*>(phd + (size_t)n * D)[hl] =
                    make_uint2(*reinterpret_cast<unsigned*>(&h0),
                               *reinterpret_cast<unsigned*>(&h1));
            }
        }
        __syncwarp();   // protect sS/sP reuse next iteration
    }
}

// ---------------- launch ----------------
extern "C" void kernel_launch(void* const* d_in, const int* in_sizes, int n_in,
                              void* d_out, int out_size) {
    (void)in_sizes; (void)n_in; (void)out_size;
    const int*   cols = (const int*)d_in[1];
    const float* vals = (const float*)d_in[2];
    const float* ue   = (const float*)d_in[3];
    const float* ie   = (const float*)d_in[4];
    float* out = (float*)d_out;

    zero_fill_kernel<<<(N_ITEMS + 255) / 256, 256>>>();
    fill2_kernel<<<(E_UI + 255) / 256, 256>>>(cols);
    ego_copy_kernel<<<(N_NODES * (D/4) + 255) / 256, 256>>>(ue, ie, out);

    int ngroups = (N_NODES + 63) / 64;   // 2344 groups of 64 nodes
    int nblk = 148 * 4;                  // grid-stride
    for (int k = 0; k < 3; k++) {
        const float* prevc = out + (size_t)64 * k;
        float*       outc  = out + (size_t)64 * (k + 1);
        const float* Ws = (const float*)d_in[5 + 4 * k + 0];
        const float* bs = (const float*)d_in[5 + 4 * k + 1];
        const float* Wp = (const float*)d_in[5 + 4 * k + 2];
        const float* bp = (const float*)d_in[5 + 4 * k + 3];
        fused_layer_kernel<<<nblk, 256>>>(cols, vals, prevc, outc,
                                          Ws, bs, Wp, bp, k & 1, ngroups);
    }
}

// round 11
// speedup vs baseline: 1.3012x; 1.3012x over previous
#include <cuda_runtime.h>
#include <cuda_fp16.h>
#include <cstdint>

// ---------------- problem constants (fixed by reference_code) ----------------
#define N_USERS 100000
#define N_ITEMS 50000
#define N_NODES 150000
#define KPU 32
#define E_UI  (N_USERS * KPU)
#define SELF_BASE (2 * E_UI)
#define D 64
#define OD 256
#define MAXDEG 128
#define TILE_M 128
#define NTILES ((N_NODES + TILE_M - 1) / TILE_M)   // 1172

// padded smem strides (halves) -> conflict-free 8-row fragment loads
#define SA_STRIDE 136
#define SW_STRIDE 136
// dynamic smem layout (bytes)
#define SM_A     0
#define SM_W     (128 * SA_STRIDE * 2)                 // 34816
#define SM_BIAS  (SM_W + 64 * SW_STRIDE * 2)           // 52224
#define SM_TOTAL (SM_BIAS + 64 * 4)                    // 52480

// ---------------- device scratch (no allocation allowed) ----------------
__device__ int g_fill[N_ITEMS];
__device__ int g_adj2[(size_t)N_ITEMS * MAXDEG];   // padded item->user lists

// ---------------- CSR build ----------------
__global__ void zero_fill_kernel() {
    int i = blockIdx.x * blockDim.x + threadIdx.x;
    if (i < N_ITEMS) g_fill[i] = 0;
}
__global__ void fill2_kernel(const int* __restrict__ cols) {
    int e = blockIdx.x * blockDim.x + threadIdx.x;
    if (e >= E_UI) return;
    int item = cols[e] - N_USERS;
    int pos  = atomicAdd(&g_fill[item], 1);
    if (pos < MAXDEG) g_adj2[item * MAXDEG + pos] = e >> 5;
}

// ---------------- ego copy: out[:,0:64] = concat(ue, ie) ----------------
__global__ void ego_copy_kernel(const float* __restrict__ ue,
                                const float* __restrict__ ie,
                                float* __restrict__ out) {
    int idx = blockIdx.x * blockDim.x + threadIdx.x;
    if (idx >= N_NODES * (D / 4)) return;
    int n  = idx >> 4;
    int c4 = idx & 15;
    float4 v = (n < N_USERS)
        ? reinterpret_cast<const float4*>(ue)[(size_t)n * (D/4) + c4]
        : reinterpret_cast<const float4*>(ie)[(size_t)(n - N_USERS) * (D/4) + c4];
    reinterpret_cast<float4*>(out)[(size_t)n * (OD/4) + c4] = v;
}

// 8-deep fp32 gather batch (proven in R8): 8 independent LDG.128, tree-reduce.
__device__ __forceinline__ void gather8(const float* __restrict__ prevc,
                                        unsigned hmask, int src, int base,
                                        int hl, float4& acc) {
    float4 v[8];
    #pragma unroll
    for (int j = 0; j < 8; j++) {
        int c = __shfl_sync(hmask, src, base + j, 16);
        v[j] = reinterpret_cast<const float4*>(prevc + (size_t)c * OD)[hl];
    }
    #pragma unroll
    for (int j = 0; j < 4; j++) {
        v[j].x += v[j+4].x; v[j].y += v[j+4].y;
        v[j].z += v[j+4].z; v[j].w += v[j+4].w;
    }
    v[0].x += v[2].x; v[0].y += v[2].y; v[0].z += v[2].z; v[0].w += v[2].w;
    v[1].x += v[3].x; v[1].y += v[3].y; v[1].z += v[3].z; v[1].w += v[3].w;
    acc.x += v[0].x + v[1].x; acc.y += v[0].y + v[1].y;
    acc.z += v[0].z + v[1].z; acc.w += v[0].w + v[1].w;
}

// warp HMMA: D[16,8] += A[16,16] * B[16,8]^T (f16 in, f32 acc)
__device__ __forceinline__ void mma16816(float* c, uint32_t a0, uint32_t a1,
                                         uint32_t a2, uint32_t a3,
                                         uint32_t b0, uint32_t b1) {
    asm volatile(
        "mma.sync.aligned.m16n8k16.row.col.f32.f16.f16.f32 "
        "{%0,%1,%2,%3}, {%4,%5,%6,%7}, {%8,%9}, {%0,%1,%2,%3};"
        : "+f"(c[0]), "+f"(c[1]), "+f"(c[2]), "+f"(c[3])
        : "r"(a0), "r"(a1), "r"(a2), "r"(a3), "r"(b0), "r"(b1));
}

// ---------------- fused layer: gather -> HMMA GEMM -> epilogue ----------------
// Tile = 128 nodes. Gather: 16 half-warps x 8 rows, staged fp16 into sA[128][136]
// as [side | side*prev] (K=128). Weights staged once per block as sW[n][k] fp16
// (n=out col 0..63, k=0..127 spanning [Ws; Wp]). 8 warps each compute a 16-row
// stripe via mma.sync m16n8k16 (8 k-steps x 8 n-tiles).
__global__ void __launch_bounds__(256, 4)
fused_layer_mma(const int* __restrict__ cols,
                const float* __restrict__ vals,
                const float* __restrict__ prevc,    // fp32, stride OD
                float* __restrict__ outc,           // fp32, stride OD
                const float* __restrict__ Ws, const float* __restrict__ bs,
                const float* __restrict__ Wp, const float* __restrict__ bp,
                int ntiles) {
    extern __shared__ char smem[];
    __half* sA    = reinterpret_cast<__half*>(smem + SM_A);
    __half* sW    = reinterpret_cast<__half*>(smem + SM_W);
    float*  sbias = reinterpret_cast<float*>(smem + SM_BIAS);

    int tx = threadIdx.x;

    // stage weights transposed: sW[n][k] = (k<64 ? Ws[k][n] : Wp[k-64][n])
    for (int idx = tx; idx < 64 * 128; idx += 256) {
        int n = idx >> 7;
        int k = idx & 127;
        float w = (k < 64) ? Ws[k * 64 + n] : Wp[(k - 64) * 64 + n];
        sW[n * SW_STRIDE + k] = __float2half_rn(w);
    }
    if (tx < 64) sbias[tx] = bs[tx] + bp[tx];

    int h  = tx >> 4;          // half-warp id (gather phase)
    int hl = tx & 15;
    unsigned hmask = 0xFFFFu << (tx & 16);
    int w    = tx >> 5;        // warp id (mma phase)
    int lane = tx & 31;
    int g    = lane >> 2;      // fragment row group
    int t    = lane & 3;       // fragment thread-in-group
    __syncthreads();

    for (int tile = blockIdx.x; tile < ntiles; tile += gridDim.x) {
        int tb = tile * TILE_M;

        // ---- Phase A: gather 8 rows per half-warp, stage fp16 ----
        #pragma unroll 2
        for (int i = 0; i < 8; i++) {
            int r = h * 8 + i;
            int n = tb + r;
            uint2* dS = reinterpret_cast<uint2*>(sA + r * SA_STRIDE + hl * 4);
            uint2* dP = reinterpret_cast<uint2*>(sA + r * SA_STRIDE + 64 + hl * 4);
            if (n >= N_NODES) {
                *dS = make_uint2(0u, 0u);
                *dP = make_uint2(0u, 0u);
                continue;
            }
            float4 pself = reinterpret_cast<const float4*>(prevc + (size_t)n * OD)[hl];
            float4 acc = pself;
            if (n < N_USERS) {
                const int* cu = cols + n * KPU;
                int c_lo = cu[hl];
                int c_hi = cu[16 + hl];
                gather8(prevc, hmask, c_lo, 0, hl, acc);
                gather8(prevc, hmask, c_lo, 8, hl, acc);
                gather8(prevc, hmask, c_hi, 0, hl, acc);
                gather8(prevc, hmask, c_hi, 8, hl, acc);
            } else {
                int it  = n - N_USERS;
                int cnt = g_fill[it]; if (cnt > MAXDEG) cnt = MAXDEG;
                const int* adj = g_adj2 + (size_t)it * MAXDEG;
                int p = 0;
                for (; p + 16 <= cnt; p += 16) {
                    int myu = adj[p + hl];
                    gather8(prevc, hmask, myu, 0, hl, acc);
                    gather8(prevc, hmask, myu, 8, hl, acc);
                }
                int rem = cnt - p;
                if (rem > 0) {
                    int myu = (hl < rem) ? adj[p + hl] : 0;
                    for (int j = 0; j < rem; j++) {
                        int uu = __shfl_sync(hmask, myu, j, 16);
                        float4 v = reinterpret_cast<const float4*>(prevc + (size_t)uu * OD)[hl];
                        acc.x += v.x; acc.y += v.y; acc.z += v.z; acc.w += v.w;
                    }
                }
            }
            float sv = vals[SELF_BASE + n];   // 1/deg[n]
            float4 sd = make_float4(acc.x*sv, acc.y*sv, acc.z*sv, acc.w*sv);
            float4 pp = make_float4(sd.x*pself.x, sd.y*pself.y, sd.z*pself.z, sd.w*pself.w);
            __half2 s0 = __floats2half2_rn(sd.x, sd.y);
            __half2 s1 = __floats2half2_rn(sd.z, sd.w);
            __half2 p0 = __floats2half2_rn(pp.x, pp.y);
            __half2 p1 = __floats2half2_rn(pp.z, pp.w);
            *dS = make_uint2(*reinterpret_cast<unsigned*>(&s0),
                             *reinterpret_cast<unsigned*>(&s1));
            *dP = make_uint2(*reinterpret_cast<unsigned*>(&p0),
                             *reinterpret_cast<unsigned*>(&p1));
        }
        __syncthreads();

        // ---- Phase B: warp stripe GEMM, rows [16w, 16w+16), via HMMA ----
        float acc[8][4];
        #pragma unroll
        for (int nt = 0; nt < 8; nt++) {
            acc[nt][0] = 0.f; acc[nt][1] = 0.f; acc[nt][2] = 0.f; acc[nt][3] = 0.f;
        }
        #pragma unroll
        for (int ks = 0; ks < 8; ks++) {
            const __half* pa = sA + (w * 16 + g) * SA_STRIDE + ks * 16 + t * 2;
            uint32_t a0 = *reinterpret_cast<const uint32_t*>(pa);
            uint32_t a1 = *reinterpret_cast<const uint32_t*>(pa + 8 * SA_STRIDE);
            uint32_t a2 = *reinterpret_cast<const uint32_t*>(pa + 8);
            uint32_t a3 = *reinterpret_cast<const uint32_t*>(pa + 8 * SA_STRIDE + 8);
            #pragma unroll
            for (int nt = 0; nt < 8; nt++) {
                const __half* pb = sW + (nt * 8 + g) * SW_STRIDE + ks * 16 + t * 2;
                uint32_t b0 = *reinterpret_cast<const uint32_t*>(pb);
                uint32_t b1 = *reinterpret_cast<const uint32_t*>(pb + 8);
                mma16816(acc[nt], a0, a1, a2, a3, b0, b1);
            }
        }

        // ---- epilogue: bias + lrelu + rowwise L2 norm + store ----
        // lane holds rows r0 = tb+16w+g (acc[][0..1]) and r1 = r0+8 (acc[][2..3]),
        // cols nt*8 + 2t, +1.
        int r0 = tb + w * 16 + g;
        int r1 = r0 + 8;
        float sq0 = 0.f, sq1 = 0.f;
        #pragma unroll
        for (int nt = 0; nt < 8; nt++) {
            float b0v = sbias[nt * 8 + t * 2];
            float b1v = sbias[nt * 8 + t * 2 + 1];
            float v;
            v = acc[nt][0] + b0v; v = (v >= 0.f) ? v : 0.2f * v; acc[nt][0] = v; sq0 += v * v;
            v = acc[nt][1] + b1v; v = (v >= 0.f) ? v : 0.2f * v; acc[nt][1] = v; sq0 += v * v;
            v = acc[nt][2] + b0v; v = (v >= 0.f) ? v : 0.2f * v; acc[nt][2] = v; sq1 += v * v;
            v = acc[nt][3] + b1v; v = (v >= 0.f) ? v : 0.2f * v; acc[nt][3] = v; sq1 += v * v;
        }
        sq0 += __shfl_xor_sync(0xffffffffu, sq0, 1);
        sq0 += __shfl_xor_sync(0xffffffffu, sq0, 2);
        sq1 += __shfl_xor_sync(0xffffffffu, sq1, 1);
        sq1 += __shfl_xor_sync(0xffffffffu, sq1, 2);
        float inv0 = 1.0f / fmaxf(sqrtf(sq0), 1e-12f);
        float inv1 = 1.0f / fmaxf(sqrtf(sq1), 1e-12f);

        if (r0 < N_NODES) {
            float* dst = outc + (size_t)r0 * OD + t * 2;
            #pragma unroll
            for (int nt = 0; nt < 8; nt++)
                *reinterpret_cast<float2*>(dst + nt * 8) =
                    make_float2(acc[nt][0] * inv0, acc[nt][1] * inv0);
        }
        if (r1 < N_NODES) {
            float* dst = outc + (size_t)r1 * OD + t * 2;
            #pragma unroll
            for (int nt = 0; nt < 8; nt++)
                *reinterpret_cast<float2*>(dst + nt * 8) =
                    make_float2(acc[nt][2] * inv1, acc[nt][3] * inv1);
        }
        __syncthreads();   // sA reused next tile
    }
}

// ---------------- launch ----------------
extern "C" void kernel_launch(void* const* d_in, const int* in_sizes, int n_in,
                              void* d_out, int out_size) {
    (void)in_sizes; (void)n_in; (void)out_size;
    const int*   cols = (const int*)d_in[1];
    const float* vals = (const float*)d_in[2];
    const float* ue   = (const float*)d_in[3];
    const float* ie   = (const float*)d_in[4];
    float* out = (float*)d_out;

    static int smem_set = 0;
    if (!smem_set) {
        cudaFuncSetAttribute(fused_layer_mma,
                             cudaFuncAttributeMaxDynamicSharedMemorySize, SM_TOTAL);
        smem_set = 1;
    }

    zero_fill_kernel<<<(N_ITEMS + 255) / 256, 256>>>();
    fill2_kernel<<<(E_UI + 255) / 256, 256>>>(cols);
    ego_copy_kernel<<<(N_NODES * (D/4) + 255) / 256, 256>>>(ue, ie, out);

    int nblk = 148 * 4;   // grid-stride, one wave at 4 CTAs/SM
    for (int k = 0; k < 3; k++) {
        const float* prevc = out + (size_t)64 * k;
        float*       outc  = out + (size_t)64 * (k + 1);
        const float* Ws = (const float*)d_in[5 + 4 * k + 0];
        const float* bs = (const float*)d_in[5 + 4 * k + 1];
        const float* Wp = (const float*)d_in[5 + 4 * k + 2];
        const float* bp = (const float*)d_in[5 + 4 * k + 3];
        fused_layer_mma<<<nblk, 256, SM_TOTAL>>>(cols, vals, prevc, outc,
                                                 Ws, bs, Wp, bp, NTILES);
    }
}

// round 12
// speedup vs baseline: 1.4923x; 1.1469x over previous
#include <cuda_runtime.h>
#include <cuda_fp16.h>
#include <cstdint>

// ---------------- problem constants (fixed by reference_code) ----------------
#define N_USERS 100000
#define N_ITEMS 50000
#define N_NODES 150000
#define KPU 32
#define E_UI  (N_USERS * KPU)
#define SELF_BASE (2 * E_UI)
#define D 64
#define OD 256
#define MAXDEG 128
#define TILE_M 128
#define NTILES ((N_NODES + TILE_M - 1) / TILE_M)   // 1172

// padded smem strides (halves) -> conflict-free fragment loads
#define SA_STRIDE 136
#define SW_STRIDE 136
// dynamic smem layout (bytes)
#define SM_A     0
#define SM_W     (128 * SA_STRIDE * 2)                 // 34816
#define SM_BIAS  (SM_W + 64 * SW_STRIDE * 2)           // 52224
#define SM_TOTAL (SM_BIAS + 64 * 4)                    // 52480

// ---------------- device scratch (no allocation allowed) ----------------
__device__ int    g_fill[N_ITEMS];
__device__ int    g_adj2[(size_t)N_ITEMS * MAXDEG];   // padded item->user lists
__device__ __half g_ph[2][(size_t)N_NODES * D];       // fp16 ping-pong gather src

// ---------------- CSR build ----------------
__global__ void zero_fill_kernel() {
    int i = blockIdx.x * blockDim.x + threadIdx.x;
    if (i < N_ITEMS) g_fill[i] = 0;
}
__global__ void fill2_kernel(const int* __restrict__ cols) {
    int e = blockIdx.x * blockDim.x + threadIdx.x;
    if (e >= E_UI) return;
    int item = cols[e] - N_USERS;
    int pos  = atomicAdd(&g_fill[item], 1);
    if (pos < MAXDEG) g_adj2[item * MAXDEG + pos] = e >> 5;
}

// ---------------- ego copy: out[:,0:64] = concat(ue, ie); fp16 pack buf 0 ----
__global__ void ego_copy_kernel(const float* __restrict__ ue,
                                const float* __restrict__ ie,
                                float* __restrict__ out) {
    int idx = blockIdx.x * blockDim.x + threadIdx.x;
    if (idx >= N_NODES * (D / 4)) return;
    int n  = idx >> 4;
    int c4 = idx & 15;
    float4 v = (n < N_USERS)
        ? reinterpret_cast<const float4*>(ue)[(size_t)n * (D/4) + c4]
        : reinterpret_cast<const float4*>(ie)[(size_t)(n - N_USERS) * (D/4) + c4];
    reinterpret_cast<float4*>(out)[(size_t)n * (OD/4) + c4] = v;
    __half2 h0 = __floats2half2_rn(v.x, v.y);
    __half2 h1 = __floats2half2_rn(v.z, v.w);
    reinterpret_cast<uint2*>(g_ph[0])[(size_t)n * (D/4) + c4] =
        make_uint2(*reinterpret_cast<unsigned*>(&h0), *reinterpret_cast<unsigned*>(&h1));
}

// 8-deep fp16 gather batch: 8 independent LDG.64 (1 L1 line per row), fp32 acc.
__device__ __forceinline__ void gather8h(const __half* __restrict__ ph,
                                         unsigned hmask, int src, int base,
                                         int hl, float4& acc) {
    uint2 v[8];
    #pragma unroll
    for (int j = 0; j < 8; j++) {
        int c = __shfl_sync(hmask, src, base + j, 16);
        v[j] = reinterpret_cast<const uint2*>(ph + (size_t)c * D)[hl];
    }
    float4 t0 = make_float4(0.f,0.f,0.f,0.f);
    float4 t1 = make_float4(0.f,0.f,0.f,0.f);
    #pragma unroll
    for (int j = 0; j < 8; j += 2) {
        float2 a0 = __half22float2(*reinterpret_cast<__half2*>(&v[j].x));
        float2 b0 = __half22float2(*reinterpret_cast<__half2*>(&v[j].y));
        float2 a1 = __half22float2(*reinterpret_cast<__half2*>(&v[j+1].x));
        float2 b1 = __half22float2(*reinterpret_cast<__half2*>(&v[j+1].y));
        t0.x += a0.x; t0.y += a0.y; t0.z += b0.x; t0.w += b0.y;
        t1.x += a1.x; t1.y += a1.y; t1.z += b1.x; t1.w += b1.y;
    }
    acc.x += t0.x + t1.x; acc.y += t0.y + t1.y;
    acc.z += t0.z + t1.z; acc.w += t0.w + t1.w;
}

// warp HMMA: D[16,8] += A[16,16] * B[16,8]^T (f16 in, f32 acc)
__device__ __forceinline__ void mma16816(float* c, uint32_t a0, uint32_t a1,
                                         uint32_t a2, uint32_t a3,
                                         uint32_t b0, uint32_t b1) {
    asm volatile(
        "mma.sync.aligned.m16n8k16.row.col.f32.f16.f16.f32 "
        "{%0,%1,%2,%3}, {%4,%5,%6,%7}, {%8,%9}, {%0,%1,%2,%3};"
        : "+f"(c[0]), "+f"(c[1]), "+f"(c[2]), "+f"(c[3])
        : "r"(a0), "r"(a1), "r"(a2), "r"(a3), "r"(b0), "r"(b1));
}

// ---------------- fused layer: fp16 gather -> HMMA GEMM -> epilogue ----------
__global__ void __launch_bounds__(256, 4)
fused_layer_mma(const int* __restrict__ cols,
                const float* __restrict__ vals,
                const float* __restrict__ prevc,    // fp32, stride OD (self rows)
                float* __restrict__ outc,           // fp32, stride OD
                const float* __restrict__ Ws, const float* __restrict__ bs,
                const float* __restrict__ Wp, const float* __restrict__ bp,
                int srcbuf, int ntiles) {
    extern __shared__ char smem[];
    __half* sA    = reinterpret_cast<__half*>(smem + SM_A);
    __half* sW    = reinterpret_cast<__half*>(smem + SM_W);
    float*  sbias = reinterpret_cast<float*>(smem + SM_BIAS);

    const __half* ph  = g_ph[srcbuf];
    __half*       phd = g_ph[srcbuf ^ 1];

    int tx = threadIdx.x;

    // stage weights transposed: sW[n][k] = (k<64 ? Ws[k][n] : Wp[k-64][n])
    for (int idx = tx; idx < 64 * 128; idx += 256) {
        int n = idx >> 7;
        int k = idx & 127;
        float w = (k < 64) ? Ws[k * 64 + n] : Wp[(k - 64) * 64 + n];
        sW[n * SW_STRIDE + k] = __float2half_rn(w);
    }
    if (tx < 64) sbias[tx] = bs[tx] + bp[tx];

    int h  = tx >> 4;          // half-warp id (gather phase)
    int hl = tx & 15;
    unsigned hmask = 0xFFFFu << (tx & 16);
    int w    = tx >> 5;        // warp id (mma phase)
    int lane = tx & 31;
    int g    = lane >> 2;      // fragment row group
    int t    = lane & 3;       // fragment thread-in-group
    __syncthreads();

    for (int tile = blockIdx.x; tile < ntiles; tile += gridDim.x) {
        int tb = tile * TILE_M;

        // ---- Phase A: gather 8 rows per half-warp (fp16 src), stage fp16 ----
        #pragma unroll 2
        for (int i = 0; i < 8; i++) {
            int r = h * 8 + i;
            int n = tb + r;
            uint2* dS = reinterpret_cast<uint2*>(sA + r * SA_STRIDE + hl * 4);
            uint2* dP = reinterpret_cast<uint2*>(sA + r * SA_STRIDE + 64 + hl * 4);
            if (n >= N_NODES) {
                *dS = make_uint2(0u, 0u);
                *dP = make_uint2(0u, 0u);
                continue;
            }
            float4 pself = reinterpret_cast<const float4*>(prevc + (size_t)n * OD)[hl];
            float4 acc = pself;   // self term exact fp32
            if (n < N_USERS) {
                const int* cu = cols + n * KPU;
                int c_lo = cu[hl];
                int c_hi = cu[16 + hl];
                gather8h(ph, hmask, c_lo, 0, hl, acc);
                gather8h(ph, hmask, c_lo, 8, hl, acc);
                gather8h(ph, hmask, c_hi, 0, hl, acc);
                gather8h(ph, hmask, c_hi, 8, hl, acc);
            } else {
                int it  = n - N_USERS;
                int cnt = g_fill[it]; if (cnt > MAXDEG) cnt = MAXDEG;
                const int* adj = g_adj2 + (size_t)it * MAXDEG;
                int p = 0;
                for (; p + 16 <= cnt; p += 16) {
                    int myu = adj[p + hl];
                    gather8h(ph, hmask, myu, 0, hl, acc);
                    gather8h(ph, hmask, myu, 8, hl, acc);
                }
                int rem = cnt - p;
                if (rem > 0) {
                    int myu = (hl < rem) ? adj[p + hl] : 0;
                    for (int j = 0; j < rem; j++) {
                        int uu = __shfl_sync(hmask, myu, j, 16);
                        uint2 u = reinterpret_cast<const uint2*>(ph + (size_t)uu * D)[hl];
                        float2 a = __half22float2(*reinterpret_cast<__half2*>(&u.x));
                        float2 b = __half22float2(*reinterpret_cast<__half2*>(&u.y));
                        acc.x += a.x; acc.y += a.y; acc.z += b.x; acc.w += b.y;
                    }
                }
            }
            float sv = vals[SELF_BASE + n];   // 1/deg[n]
            float4 sd = make_float4(acc.x*sv, acc.y*sv, acc.z*sv, acc.w*sv);
            float4 pp = make_float4(sd.x*pself.x, sd.y*pself.y, sd.z*pself.z, sd.w*pself.w);
            __half2 s0 = __floats2half2_rn(sd.x, sd.y);
            __half2 s1 = __floats2half2_rn(sd.z, sd.w);
            __half2 p0 = __floats2half2_rn(pp.x, pp.y);
            __half2 p1 = __floats2half2_rn(pp.z, pp.w);
            *dS = make_uint2(*reinterpret_cast<unsigned*>(&s0),
                             *reinterpret_cast<unsigned*>(&s1));
            *dP = make_uint2(*reinterpret_cast<unsigned*>(&p0),
                             *reinterpret_cast<unsigned*>(&p1));
        }
        __syncthreads();

        // ---- Phase B: warp stripe GEMM, rows [16w, 16w+16), via HMMA ----
        float acc[8][4];
        #pragma unroll
        for (int nt = 0; nt < 8; nt++) {
            acc[nt][0] = 0.f; acc[nt][1] = 0.f; acc[nt][2] = 0.f; acc[nt][3] = 0.f;
        }
        #pragma unroll
        for (int ks = 0; ks < 8; ks++) {
            const __half* pa = sA + (w * 16 + g) * SA_STRIDE + ks * 16 + t * 2;
            uint32_t a0 = *reinterpret_cast<const uint32_t*>(pa);
            uint32_t a1 = *reinterpret_cast<const uint32_t*>(pa + 8 * SA_STRIDE);
            uint32_t a2 = *reinterpret_cast<const uint32_t*>(pa + 8);
            uint32_t a3 = *reinterpret_cast<const uint32_t*>(pa + 8 * SA_STRIDE + 8);
            #pragma unroll
            for (int nt = 0; nt < 8; nt++) {
                const __half* pb = sW + (nt * 8 + g) * SW_STRIDE + ks * 16 + t * 2;
                uint32_t b0 = *reinterpret_cast<const uint32_t*>(pb);
                uint32_t b1 = *reinterpret_cast<const uint32_t*>(pb + 8);
                mma16816(acc[nt], a0, a1, a2, a3, b0, b1);
            }
        }

        // ---- epilogue: bias + lrelu + rowwise L2 norm + fp32/fp16 stores ----
        int r0 = tb + w * 16 + g;
        int r1 = r0 + 8;
        float sq0 = 0.f, sq1 = 0.f;
        #pragma unroll
        for (int nt = 0; nt < 8; nt++) {
            float b0v = sbias[nt * 8 + t * 2];
            float b1v = sbias[nt * 8 + t * 2 + 1];
            float v;
            v = acc[nt][0] + b0v; v = (v >= 0.f) ? v : 0.2f * v; acc[nt][0] = v; sq0 += v * v;
            v = acc[nt][1] + b1v; v = (v >= 0.f) ? v : 0.2f * v; acc[nt][1] = v; sq0 += v * v;
            v = acc[nt][2] + b0v; v = (v >= 0.f) ? v : 0.2f * v; acc[nt][2] = v; sq1 += v * v;
            v = acc[nt][3] + b1v; v = (v >= 0.f) ? v : 0.2f * v; acc[nt][3] = v; sq1 += v * v;
        }
        sq0 += __shfl_xor_sync(0xffffffffu, sq0, 1);
        sq0 += __shfl_xor_sync(0xffffffffu, sq0, 2);
        sq1 += __shfl_xor_sync(0xffffffffu, sq1, 1);
        sq1 += __shfl_xor_sync(0xffffffffu, sq1, 2);
        float inv0 = 1.0f / fmaxf(sqrtf(sq0), 1e-12f);
        float inv1 = 1.0f / fmaxf(sqrtf(sq1), 1e-12f);

        if (r0 < N_NODES) {
            float*  dst = outc + (size_t)r0 * OD + t * 2;
            __half* hd  = phd + (size_t)r0 * D + t * 2;
            #pragma unroll
            for (int nt = 0; nt < 8; nt++) {
                float2 o = make_float2(acc[nt][0] * inv0, acc[nt][1] * inv0);
                *reinterpret_cast<float2*>(dst + nt * 8) = o;
                __half2 hh = __floats2half2_rn(o.x, o.y);
                *reinterpret_cast<__half2*>(hd + nt * 8) = hh;
            }
        }
        if (r1 < N_NODES) {
            float*  dst = outc + (size_t)r1 * OD + t * 2;
            __half* hd  = phd + (size_t)r1 * D + t * 2;
            #pragma unroll
            for (int nt = 0; nt < 8; nt++) {
                float2 o = make_float2(acc[nt][2] * inv1, acc[nt][3] * inv1);
                *reinterpret_cast<float2*>(dst + nt * 8) = o;
                __half2 hh = __floats2half2_rn(o.x, o.y);
                *reinterpret_cast<__half2*>(hd + nt * 8) = hh;
            }
        }
        __syncthreads();   // sA reused next tile
    }
}

// ---------------- launch ----------------
extern "C" void kernel_launch(void* const* d_in, const int* in_sizes, int n_in,
                              void* d_out, int out_size) {
    (void)in_sizes; (void)n_in; (void)out_size;
    const int*   cols = (const int*)d_in[1];
    const float* vals = (const float*)d_in[2];
    const float* ue   = (const float*)d_in[3];
    const float* ie   = (const float*)d_in[4];
    float* out = (float*)d_out;

    static int smem_set = 0;
    if (!smem_set) {
        cudaFuncSetAttribute(fused_layer_mma,
                             cudaFuncAttributeMaxDynamicSharedMemorySize, SM_TOTAL);
        smem_set = 1;
    }

    zero_fill_kernel<<<(N_ITEMS + 255) / 256, 256>>>();
    fill2_kernel<<<(E_UI + 255) / 256, 256>>>(cols);
    ego_copy_kernel<<<(N_NODES * (D/4) + 255) / 256, 256>>>(ue, ie, out);

    int nblk = 148 * 4;   // grid-stride, one wave at 4 CTAs/SM
    for (int k = 0; k < 3; k++) {
        const float* prevc = out + (size_t)64 * k;
        float*       outc  = out + (size_t)64 * (k + 1);
        const float* Ws = (const float*)d_in[5 + 4 * k + 0];
        const float* bs = (const float*)d_in[5 + 4 * k + 1];
        const float* Wp = (const float*)d_in[5 + 4 * k + 2];
        const float* bp = (const float*)d_in[5 + 4 * k + 3];
        fused_layer_mma<<<nblk, 256, SM_TOTAL>>>(cols, vals, prevc, outc,
                                                 Ws, bs, Wp, bp, k & 1, NTILES);
    }
}

// round 13
// speedup vs baseline: 1.6368x; 1.0968x over previous
#include <cuda_runtime.h>
#include <cuda_fp16.h>
#include <cstdint>

// ---------------- problem constants (fixed by reference_code) ----------------
#define N_USERS 100000
#define N_ITEMS 50000
#define N_NODES 150000
#define KPU 32
#define E_UI  (N_USERS * KPU)
#define SELF_BASE (2 * E_UI)
#define D 64
#define OD 256
#define MAXDEG 128
#define TILE_M 128
#define NTILES ((N_NODES + TILE_M - 1) / TILE_M)   // 1172

// padded smem strides (halves) -> conflict-free fragment loads
#define SA_STRIDE 136
#define SW_STRIDE 136
// dynamic smem layout (bytes)
#define SM_A     0
#define SM_W     (128 * SA_STRIDE * 2)                 // 34816
#define SM_BIAS  (SM_W + 64 * SW_STRIDE * 2)           // 52224
#define SM_TOTAL (SM_BIAS + 64 * 4)                    // 52480

// ---------------- device scratch (no allocation allowed) ----------------
__device__ int    g_fill[N_ITEMS];
__device__ int    g_adj2[(size_t)N_ITEMS * MAXDEG];   // padded item->user lists
__device__ __align__(128) __half g_ph[2][(size_t)N_NODES * D];  // fp16 ping-pong

#define H2(u) (*reinterpret_cast<const __half2*>(&(u)))

// ---------------- CSR build ----------------
__global__ void zero_fill_kernel() {
    int i = blockIdx.x * blockDim.x + threadIdx.x;
    if (i < N_ITEMS) g_fill[i] = 0;
}
__global__ void fill2_kernel(const int* __restrict__ cols) {
    int e = blockIdx.x * blockDim.x + threadIdx.x;
    if (e >= E_UI) return;
    int item = cols[e] - N_USERS;
    int pos  = atomicAdd(&g_fill[item], 1);
    if (pos < MAXDEG) g_adj2[item * MAXDEG + pos] = e >> 5;
}

// ---------------- ego copy: out[:,0:64] = concat(ue, ie); fp16 pack buf 0 ----
__global__ void ego_copy_kernel(const float* __restrict__ ue,
                                const float* __restrict__ ie,
                                float* __restrict__ out) {
    int idx = blockIdx.x * blockDim.x + threadIdx.x;
    if (idx >= N_NODES * (D / 4)) return;
    int n  = idx >> 4;
    int c4 = idx & 15;
    float4 v = (n < N_USERS)
        ? reinterpret_cast<const float4*>(ue)[(size_t)n * (D/4) + c4]
        : reinterpret_cast<const float4*>(ie)[(size_t)(n - N_USERS) * (D/4) + c4];
    reinterpret_cast<float4*>(out)[(size_t)n * (OD/4) + c4] = v;
    __half2 h0 = __floats2half2_rn(v.x, v.y);
    __half2 h1 = __floats2half2_rn(v.z, v.w);
    reinterpret_cast<uint2*>(g_ph[0])[(size_t)n * (D/4) + c4] =
        make_uint2(*reinterpret_cast<unsigned*>(&h0), *reinterpret_cast<unsigned*>(&h1));
}

// 8-deep fp16 gather batch: 8 independent LDG.64, fp16 tree-sum, fp32 hand-off.
__device__ __forceinline__ void gather8h(const __half* __restrict__ ph,
                                         unsigned hmask, int src, int base,
                                         int hl, float4& acc) {
    uint2 v[8];
    #pragma unroll
    for (int j = 0; j < 8; j++) {
        int c = __shfl_sync(hmask, src, base + j, 16);
        v[j] = reinterpret_cast<const uint2*>(ph + (size_t)c * D)[hl];
    }
    __half2 l01 = __hadd2(H2(v[0].x), H2(v[1].x));
    __half2 l23 = __hadd2(H2(v[2].x), H2(v[3].x));
    __half2 l45 = __hadd2(H2(v[4].x), H2(v[5].x));
    __half2 l67 = __hadd2(H2(v[6].x), H2(v[7].x));
    __half2 h01 = __hadd2(H2(v[0].y), H2(v[1].y));
    __half2 h23 = __hadd2(H2(v[2].y), H2(v[3].y));
    __half2 h45 = __hadd2(H2(v[4].y), H2(v[5].y));
    __half2 h67 = __hadd2(H2(v[6].y), H2(v[7].y));
    __half2 lo = __hadd2(__hadd2(l01, l23), __hadd2(l45, l67));
    __half2 hi = __hadd2(__hadd2(h01, h23), __hadd2(h45, h67));
    float2 fl = __half22float2(lo);
    float2 fh = __half22float2(hi);
    acc.x += fl.x; acc.y += fl.y; acc.z += fh.x; acc.w += fh.y;
}

// warp HMMA: D[16,8] += A[16,16] * B[16,8]^T (f16 in, f32 acc)
__device__ __forceinline__ void mma16816(float* c, uint32_t a0, uint32_t a1,
                                         uint32_t a2, uint32_t a3,
                                         uint32_t b0, uint32_t b1) {
    asm volatile(
        "mma.sync.aligned.m16n8k16.row.col.f32.f16.f16.f32 "
        "{%0,%1,%2,%3}, {%4,%5,%6,%7}, {%8,%9}, {%0,%1,%2,%3};"
        : "+f"(c[0]), "+f"(c[1]), "+f"(c[2]), "+f"(c[3])
        : "r"(a0), "r"(a1), "r"(a2), "r"(a3), "r"(b0), "r"(b1));
}

// ---------------- fused layer: fp16 gather -> HMMA GEMM -> epilogue ----------
__global__ void __launch_bounds__(256, 4)
fused_layer_mma(const int* __restrict__ cols,
                const float* __restrict__ vals,
                float* __restrict__ outc,           // fp32, stride OD
                const float* __restrict__ Ws, const float* __restrict__ bs,
                const float* __restrict__ Wp, const float* __restrict__ bp,
                int srcbuf, int ntiles) {
    extern __shared__ char smem[];
    __half* sA    = reinterpret_cast<__half*>(smem + SM_A);
    __half* sW    = reinterpret_cast<__half*>(smem + SM_W);
    float*  sbias = reinterpret_cast<float*>(smem + SM_BIAS);

    const __half* ph  = g_ph[srcbuf];
    __half*       phd = g_ph[srcbuf ^ 1];

    int tx = threadIdx.x;

    // stage weights transposed: sW[n][k] = (k<64 ? Ws[k][n] : Wp[k-64][n])
    for (int idx = tx; idx < 64 * 128; idx += 256) {
        int n = idx >> 7;
        int k = idx & 127;
        float w = (k < 64) ? Ws[k * 64 + n] : Wp[(k - 64) * 64 + n];
        sW[n * SW_STRIDE + k] = __float2half_rn(w);
    }
    if (tx < 64) sbias[tx] = bs[tx] + bp[tx];

    int h  = tx >> 4;          // half-warp id (gather phase)
    int hl = tx & 15;
    unsigned hmask = 0xFFFFu << (tx & 16);
    int w    = tx >> 5;        // warp id (mma phase)
    int lane = tx & 31;
    int g    = lane >> 2;      // fragment row group
    int t    = lane & 3;       // fragment thread-in-group
    __syncthreads();

    for (int tile = blockIdx.x; tile < ntiles; tile += gridDim.x) {
        int tb = tile * TILE_M;

        // ---- Phase A: gather 8 rows per half-warp (all-fp16 src), stage ----
        #pragma unroll 2
        for (int i = 0; i < 8; i++) {
            int r = h * 8 + i;
            int n = tb + r;
            uint2* dS = reinterpret_cast<uint2*>(sA + r * SA_STRIDE + hl * 4);
            uint2* dP = reinterpret_cast<uint2*>(sA + r * SA_STRIDE + 64 + hl * 4);
            if (n >= N_NODES) {
                *dS = make_uint2(0u, 0u);
                *dP = make_uint2(0u, 0u);
                continue;
            }
            // self row from fp16 buffer (1 L1 line); also used for the pair term
            uint2 us = reinterpret_cast<const uint2*>(ph + (size_t)n * D)[hl];
            float2 sa = __half22float2(H2(us.x));
            float2 sb = __half22float2(H2(us.y));
            float4 pself = make_float4(sa.x, sa.y, sb.x, sb.y);
            float4 acc = pself;
            if (n < N_USERS) {
                const int* cu = cols + n * KPU;
                int c_lo = cu[hl];
                int c_hi = cu[16 + hl];
                gather8h(ph, hmask, c_lo, 0, hl, acc);
                gather8h(ph, hmask, c_lo, 8, hl, acc);
                gather8h(ph, hmask, c_hi, 0, hl, acc);
                gather8h(ph, hmask, c_hi, 8, hl, acc);
            } else {
                int it  = n - N_USERS;
                int cnt = g_fill[it]; if (cnt > MAXDEG) cnt = MAXDEG;
                const int* adj = g_adj2 + (size_t)it * MAXDEG;
                int p = 0;
                for (; p + 16 <= cnt; p += 16) {
                    int myu = adj[p + hl];
                    gather8h(ph, hmask, myu, 0, hl, acc);
                    gather8h(ph, hmask, myu, 8, hl, acc);
                }
                int rem = cnt - p;
                if (rem > 0) {
                    int myu = (hl < rem) ? adj[p + hl] : 0;
                    for (int j = 0; j < rem; j++) {
                        int uu = __shfl_sync(hmask, myu, j, 16);
                        uint2 u = reinterpret_cast<const uint2*>(ph + (size_t)uu * D)[hl];
                        float2 a = __half22float2(H2(u.x));
                        float2 b = __half22float2(H2(u.y));
                        acc.x += a.x; acc.y += a.y; acc.z += b.x; acc.w += b.y;
                    }
                }
            }
            float sv = vals[SELF_BASE + n];   // 1/deg[n]
            float4 sd = make_float4(acc.x*sv, acc.y*sv, acc.z*sv, acc.w*sv);
            float4 pp = make_float4(sd.x*pself.x, sd.y*pself.y, sd.z*pself.z, sd.w*pself.w);
            __half2 s0 = __floats2half2_rn(sd.x, sd.y);
            __half2 s1 = __floats2half2_rn(sd.z, sd.w);
            __half2 p0 = __floats2half2_rn(pp.x, pp.y);
            __half2 p1 = __floats2half2_rn(pp.z, pp.w);
            *dS = make_uint2(*reinterpret_cast<unsigned*>(&s0),
                             *reinterpret_cast<unsigned*>(&s1));
            *dP = make_uint2(*reinterpret_cast<unsigned*>(&p0),
                             *reinterpret_cast<unsigned*>(&p1));
        }
        __syncthreads();

        // ---- Phase B: warp stripe GEMM, rows [16w, 16w+16), via HMMA ----
        float acc[8][4];
        #pragma unroll
        for (int nt = 0; nt < 8; nt++) {
            acc[nt][0] = 0.f; acc[nt][1] = 0.f; acc[nt][2] = 0.f; acc[nt][3] = 0.f;
        }
        #pragma unroll
        for (int ks = 0; ks < 8; ks++) {
            const __half* pa = sA + (w * 16 + g) * SA_STRIDE + ks * 16 + t * 2;
            uint32_t a0 = *reinterpret_cast<const uint32_t*>(pa);
            uint32_t a1 = *reinterpret_cast<const uint32_t*>(pa + 8 * SA_STRIDE);
            uint32_t a2 = *reinterpret_cast<const uint32_t*>(pa + 8);
            uint32_t a3 = *reinterpret_cast<const uint32_t*>(pa + 8 * SA_STRIDE + 8);
            #pragma unroll
            for (int nt = 0; nt < 8; nt++) {
                const __half* pb = sW + (nt * 8 + g) * SW_STRIDE + ks * 16 + t * 2;
                uint32_t b0 = *reinterpret_cast<const uint32_t*>(pb);
                uint32_t b1 = *reinterpret_cast<const uint32_t*>(pb + 8);
                mma16816(acc[nt], a0, a1, a2, a3, b0, b1);
            }
        }

        // ---- epilogue: bias + lrelu + rowwise L2 norm + fp32/fp16 stores ----
        int r0 = tb + w * 16 + g;
        int r1 = r0 + 8;
        float sq0 = 0.f, sq1 = 0.f;
        #pragma unroll
        for (int nt = 0; nt < 8; nt++) {
            float b0v = sbias[nt * 8 + t * 2];
            float b1v = sbias[nt * 8 + t * 2 + 1];
            float v;
            v = acc[nt][0] + b0v; v = (v >= 0.f) ? v : 0.2f * v; acc[nt][0] = v; sq0 += v * v;
            v = acc[nt][1] + b1v; v = (v >= 0.f) ? v : 0.2f * v; acc[nt][1] = v; sq0 += v * v;
            v = acc[nt][2] + b0v; v = (v >= 0.f) ? v : 0.2f * v; acc[nt][2] = v; sq1 += v * v;
            v = acc[nt][3] + b1v; v = (v >= 0.f) ? v : 0.2f * v; acc[nt][3] = v; sq1 += v * v;
        }
        sq0 += __shfl_xor_sync(0xffffffffu, sq0, 1);
        sq0 += __shfl_xor_sync(0xffffffffu, sq0, 2);
        sq1 += __shfl_xor_sync(0xffffffffu, sq1, 1);
        sq1 += __shfl_xor_sync(0xffffffffu, sq1, 2);
        float inv0 = 1.0f / fmaxf(sqrtf(sq0), 1e-12f);
        float inv1 = 1.0f / fmaxf(sqrtf(sq1), 1e-12f);

        if (r0 < N_NODES) {
            float*  dst = outc + (size_t)r0 * OD + t * 2;
            __half* hd  = phd + (size_t)r0 * D + t * 2;
            #pragma unroll
            for (int nt = 0; nt < 8; nt++) {
                float2 o = make_float2(acc[nt][0] * inv0, acc[nt][1] * inv0);
                *reinterpret_cast<float2*>(dst + nt * 8) = o;
                __half2 hh = __floats2half2_rn(o.x, o.y);
                *reinterpret_cast<__half2*>(hd + nt * 8) = hh;
            }
        }
        if (r1 < N_NODES) {
            float*  dst = outc + (size_t)r1 * OD + t * 2;
            __half* hd  = phd + (size_t)r1 * D + t * 2;
            #pragma unroll
            for (int nt = 0; nt < 8; nt++) {
                float2 o = make_float2(acc[nt][2] * inv1, acc[nt][3] * inv1);
                *reinterpret_cast<float2*>(dst + nt * 8) = o;
                __half2 hh = __floats2half2_rn(o.x, o.y);
                *reinterpret_cast<__half2*>(hd + nt * 8) = hh;
            }
        }
        __syncthreads();   // sA reused next tile
    }
}

// ---------------- launch ----------------
extern "C" void kernel_launch(void* const* d_in, const int* in_sizes, int n_in,
                              void* d_out, int out_size) {
    (void)in_sizes; (void)n_in; (void)out_size;
    const int*   cols = (const int*)d_in[1];
    const float* vals = (const float*)d_in[2];
    const float* ue   = (const float*)d_in[3];
    const float* ie   = (const float*)d_in[4];
    float* out = (float*)d_out;

    static int smem_set = 0;
    if (!smem_set) {
        cudaFuncSetAttribute(fused_layer_mma,
                             cudaFuncAttributeMaxDynamicSharedMemorySize, SM_TOTAL);
        smem_set = 1;
    }

    zero_fill_kernel<<<(N_ITEMS + 255) / 256, 256>>>();
    fill2_kernel<<<(E_UI + 255) / 256, 256>>>(cols);
    ego_copy_kernel<<<(N_NODES * (D/4) + 255) / 256, 256>>>(ue, ie, out);

    int nblk = 148 * 4;   // grid-stride, one wave at 4 CTAs/SM
    for (int k = 0; k < 3; k++) {
        float* outc = out + (size_t)64 * (k + 1);
        const float* Ws = (const float*)d_in[5 + 4 * k + 0];
        const float* bs = (const float*)d_in[5 + 4 * k + 1];
        const float* Wp = (const float*)d_in[5 + 4 * k + 2];
        const float* bp = (const float*)d_in[5 + 4 * k + 3];
        fused_layer_mma<<<nblk, 256, SM_TOTAL>>>(cols, vals, outc,
                                                 Ws, bs, Wp, bp, k & 1, NTILES);
    }
}

// round 14
// speedup vs baseline: 1.7097x; 1.0445x over previous
#include <cuda_runtime.h>
#include <cuda_fp16.h>
#include <cstdint>

// ---------------- problem constants (fixed by reference_code) ----------------
#define N_USERS 100000
#define N_ITEMS 50000
#define N_NODES 150000
#define KPU 32
#define E_UI  (N_USERS * KPU)
#define SELF_BASE (2 * E_UI)
#define D 64
#define OD 256
#define MAXDEG 128
#define TILE_M 128
#define NTILES ((N_NODES + TILE_M - 1) / TILE_M)   // 1172

// padded smem strides (halves) -> conflict-free fragment loads
#define SA_STRIDE 136
#define SW_STRIDE 136
#define SF_STRIDE 68            // float stride for epilogue bounce (aliases sA)
// dynamic smem layout (bytes)
#define SM_A     0
#define SM_W     (128 * SA_STRIDE * 2)                 // 34816
#define SM_BIAS  (SM_W + 64 * SW_STRIDE * 2)           // 52224
#define SM_TOTAL (SM_BIAS + 64 * 4)                    // 52480

// ---------------- device scratch (no allocation allowed) ----------------
__device__ int    g_fill[N_ITEMS];
__device__ int    g_adj2[(size_t)N_ITEMS * MAXDEG];   // padded item->user lists
__device__ __align__(128) __half g_ph[2][(size_t)N_NODES * D];  // fp16 ping-pong

#define H2(u) (*reinterpret_cast<const __half2*>(&(u)))

// ---------------- CSR build ----------------
__global__ void zero_fill_kernel() {
    int i = blockIdx.x * blockDim.x + threadIdx.x;
    if (i < N_ITEMS) g_fill[i] = 0;
}
__global__ void fill2_kernel(const int* __restrict__ cols) {
    int e = blockIdx.x * blockDim.x + threadIdx.x;
    if (e >= E_UI) return;
    int item = cols[e] - N_USERS;
    int pos  = atomicAdd(&g_fill[item], 1);
    if (pos < MAXDEG) g_adj2[item * MAXDEG + pos] = e >> 5;
}

// ---------------- ego copy: out[:,0:64] = concat(ue, ie); fp16 pack buf 0 ----
__global__ void ego_copy_kernel(const float* __restrict__ ue,
                                const float* __restrict__ ie,
                                float* __restrict__ out) {
    int idx = blockIdx.x * blockDim.x + threadIdx.x;
    if (idx >= N_NODES * (D / 4)) return;
    int n  = idx >> 4;
    int c4 = idx & 15;
    float4 v = (n < N_USERS)
        ? reinterpret_cast<const float4*>(ue)[(size_t)n * (D/4) + c4]
        : reinterpret_cast<const float4*>(ie)[(size_t)(n - N_USERS) * (D/4) + c4];
    reinterpret_cast<float4*>(out)[(size_t)n * (OD/4) + c4] = v;
    __half2 h0 = __floats2half2_rn(v.x, v.y);
    __half2 h1 = __floats2half2_rn(v.z, v.w);
    reinterpret_cast<uint2*>(g_ph[0])[(size_t)n * (D/4) + c4] =
        make_uint2(*reinterpret_cast<unsigned*>(&h0), *reinterpret_cast<unsigned*>(&h1));
}

// 8-deep fp16 gather batch: 8 independent LDG.64, fp16 tree-sum, fp32 hand-off.
__device__ __forceinline__ void gather8h(const __half* __restrict__ ph,
                                         unsigned hmask, int src, int base,
                                         int hl, float4& acc) {
    uint2 v[8];
    #pragma unroll
    for (int j = 0; j < 8; j++) {
        int c = __shfl_sync(hmask, src, base + j, 16);
        v[j] = reinterpret_cast<const uint2*>(ph + (size_t)c * D)[hl];
    }
    __half2 l01 = __hadd2(H2(v[0].x), H2(v[1].x));
    __half2 l23 = __hadd2(H2(v[2].x), H2(v[3].x));
    __half2 l45 = __hadd2(H2(v[4].x), H2(v[5].x));
    __half2 l67 = __hadd2(H2(v[6].x), H2(v[7].x));
    __half2 h01 = __hadd2(H2(v[0].y), H2(v[1].y));
    __half2 h23 = __hadd2(H2(v[2].y), H2(v[3].y));
    __half2 h45 = __hadd2(H2(v[4].y), H2(v[5].y));
    __half2 h67 = __hadd2(H2(v[6].y), H2(v[7].y));
    __half2 lo = __hadd2(__hadd2(l01, l23), __hadd2(l45, l67));
    __half2 hi = __hadd2(__hadd2(h01, h23), __hadd2(h45, h67));
    float2 fl = __half22float2(lo);
    float2 fh = __half22float2(hi);
    acc.x += fl.x; acc.y += fl.y; acc.z += fh.x; acc.w += fh.y;
}

// warp HMMA: D[16,8] += A[16,16] * B[16,8]^T (f16 in, f32 acc)
__device__ __forceinline__ void mma16816(float* c, uint32_t a0, uint32_t a1,
                                         uint32_t a2, uint32_t a3,
                                         uint32_t b0, uint32_t b1) {
    asm volatile(
        "mma.sync.aligned.m16n8k16.row.col.f32.f16.f16.f32 "
        "{%0,%1,%2,%3}, {%4,%5,%6,%7}, {%8,%9}, {%0,%1,%2,%3};"
        : "+f"(c[0]), "+f"(c[1]), "+f"(c[2]), "+f"(c[3])
        : "r"(a0), "r"(a1), "r"(a2), "r"(a3), "r"(b0), "r"(b1));
}

// ---------------- fused layer: fp16 gather -> HMMA GEMM -> epilogue ----------
__global__ void __launch_bounds__(256, 4)
fused_layer_mma(const int* __restrict__ cols,
                const float* __restrict__ vals,
                float* __restrict__ outc,           // fp32, stride OD
                const float* __restrict__ Ws, const float* __restrict__ bs,
                const float* __restrict__ Wp, const float* __restrict__ bp,
                int srcbuf, int ntiles) {
    extern __shared__ char smem[];
    __half* sA    = reinterpret_cast<__half*>(smem + SM_A);
    float*  sF    = reinterpret_cast<float*>(smem + SM_A);   // epilogue bounce (aliases sA)
    __half* sW    = reinterpret_cast<__half*>(smem + SM_W);
    float*  sbias = reinterpret_cast<float*>(smem + SM_BIAS);

    const __half* ph  = g_ph[srcbuf];
    __half*       phd = g_ph[srcbuf ^ 1];

    int tx = threadIdx.x;

    // stage weights transposed: sW[n][k] = (k<64 ? Ws[k][n] : Wp[k-64][n])
    for (int idx = tx; idx < 64 * 128; idx += 256) {
        int n = idx >> 7;
        int k = idx & 127;
        float w = (k < 64) ? Ws[k * 64 + n] : Wp[(k - 64) * 64 + n];
        sW[n * SW_STRIDE + k] = __float2half_rn(w);
    }
    if (tx < 64) sbias[tx] = bs[tx] + bp[tx];

    int h  = tx >> 4;          // half-warp id (gather/writeout phases)
    int hl = tx & 15;
    unsigned hmask = 0xFFFFu << (tx & 16);
    int w    = tx >> 5;        // warp id (mma phase)
    int lane = tx & 31;
    int g    = lane >> 2;      // fragment row group
    int t    = lane & 3;       // fragment thread-in-group
    __syncthreads();

    for (int tile = blockIdx.x; tile < ntiles; tile += gridDim.x) {
        int tb = tile * TILE_M;

        // ---- Phase A: gather 8 rows per half-warp (all-fp16 src), stage ----
        #pragma unroll 2
        for (int i = 0; i < 8; i++) {
            int r = h * 8 + i;
            int n = tb + r;
            uint2* dS = reinterpret_cast<uint2*>(sA + r * SA_STRIDE + hl * 4);
            uint2* dP = reinterpret_cast<uint2*>(sA + r * SA_STRIDE + 64 + hl * 4);
            if (n >= N_NODES) {
                *dS = make_uint2(0u, 0u);
                *dP = make_uint2(0u, 0u);
                continue;
            }
            uint2 us = reinterpret_cast<const uint2*>(ph + (size_t)n * D)[hl];
            float2 sa = __half22float2(H2(us.x));
            float2 sb = __half22float2(H2(us.y));
            float4 pself = make_float4(sa.x, sa.y, sb.x, sb.y);
            float4 acc = pself;
            if (n < N_USERS) {
                const int* cu = cols + n * KPU;
                int c_lo = cu[hl];
                int c_hi = cu[16 + hl];
                gather8h(ph, hmask, c_lo, 0, hl, acc);
                gather8h(ph, hmask, c_lo, 8, hl, acc);
                gather8h(ph, hmask, c_hi, 0, hl, acc);
                gather8h(ph, hmask, c_hi, 8, hl, acc);
            } else {
                int it  = n - N_USERS;
                int cnt = g_fill[it]; if (cnt > MAXDEG) cnt = MAXDEG;
                const int* adj = g_adj2 + (size_t)it * MAXDEG;
                int p = 0;
                for (; p + 16 <= cnt; p += 16) {
                    int myu = adj[p + hl];
                    gather8h(ph, hmask, myu, 0, hl, acc);
                    gather8h(ph, hmask, myu, 8, hl, acc);
                }
                int rem = cnt - p;
                if (rem > 0) {
                    int myu = (hl < rem) ? adj[p + hl] : 0;
                    for (int j = 0; j < rem; j++) {
                        int uu = __shfl_sync(hmask, myu, j, 16);
                        uint2 u = reinterpret_cast<const uint2*>(ph + (size_t)uu * D)[hl];
                        float2 a = __half22float2(H2(u.x));
                        float2 b = __half22float2(H2(u.y));
                        acc.x += a.x; acc.y += a.y; acc.z += b.x; acc.w += b.y;
                    }
                }
            }
            float sv = vals[SELF_BASE + n];   // 1/deg[n]
            float4 sd = make_float4(acc.x*sv, acc.y*sv, acc.z*sv, acc.w*sv);
            float4 pp = make_float4(sd.x*pself.x, sd.y*pself.y, sd.z*pself.z, sd.w*pself.w);
            __half2 s0 = __floats2half2_rn(sd.x, sd.y);
            __half2 s1 = __floats2half2_rn(sd.z, sd.w);
            __half2 p0 = __floats2half2_rn(pp.x, pp.y);
            __half2 p1 = __floats2half2_rn(pp.z, pp.w);
            *dS = make_uint2(*reinterpret_cast<unsigned*>(&s0),
                             *reinterpret_cast<unsigned*>(&s1));
            *dP = make_uint2(*reinterpret_cast<unsigned*>(&p0),
                             *reinterpret_cast<unsigned*>(&p1));
        }
        __syncthreads();

        // ---- Phase B: warp stripe GEMM, rows [16w, 16w+16), via HMMA ----
        float acc[8][4];
        #pragma unroll
        for (int nt = 0; nt < 8; nt++) {
            acc[nt][0] = 0.f; acc[nt][1] = 0.f; acc[nt][2] = 0.f; acc[nt][3] = 0.f;
        }
        #pragma unroll
        for (int ks = 0; ks < 8; ks++) {
            const __half* pa = sA + (w * 16 + g) * SA_STRIDE + ks * 16 + t * 2;
            uint32_t a0 = *reinterpret_cast<const uint32_t*>(pa);
            uint32_t a1 = *reinterpret_cast<const uint32_t*>(pa + 8 * SA_STRIDE);
            uint32_t a2 = *reinterpret_cast<const uint32_t*>(pa + 8);
            uint32_t a3 = *reinterpret_cast<const uint32_t*>(pa + 8 * SA_STRIDE + 8);
            #pragma unroll
            for (int nt = 0; nt < 8; nt++) {
                const __half* pb = sW + (nt * 8 + g) * SW_STRIDE + ks * 16 + t * 2;
                uint32_t b0 = *reinterpret_cast<const uint32_t*>(pb);
                uint32_t b1 = *reinterpret_cast<const uint32_t*>(pb + 8);
                mma16816(acc[nt], a0, a1, a2, a3, b0, b1);
            }
        }

        // ---- epilogue: bias + lrelu + L2 norm, bounce through smem ----
        // Each warp overwrites only its own Phase-B rows [16w,16w+16) of sF(=sA):
        // warp-internal ordering makes this safe without an extra barrier.
        {
            int lr0 = w * 16 + g;        // local rows
            int lr1 = lr0 + 8;
            float sq0 = 0.f, sq1 = 0.f;
            #pragma unroll
            for (int nt = 0; nt < 8; nt++) {
                float b0v = sbias[nt * 8 + t * 2];
                float b1v = sbias[nt * 8 + t * 2 + 1];
                float v;
                v = acc[nt][0] + b0v; v = (v >= 0.f) ? v : 0.2f * v; acc[nt][0] = v; sq0 += v * v;
                v = acc[nt][1] + b1v; v = (v >= 0.f) ? v : 0.2f * v; acc[nt][1] = v; sq0 += v * v;
                v = acc[nt][2] + b0v; v = (v >= 0.f) ? v : 0.2f * v; acc[nt][2] = v; sq1 += v * v;
                v = acc[nt][3] + b1v; v = (v >= 0.f) ? v : 0.2f * v; acc[nt][3] = v; sq1 += v * v;
            }
            sq0 += __shfl_xor_sync(0xffffffffu, sq0, 1);
            sq0 += __shfl_xor_sync(0xffffffffu, sq0, 2);
            sq1 += __shfl_xor_sync(0xffffffffu, sq1, 1);
            sq1 += __shfl_xor_sync(0xffffffffu, sq1, 2);
            float inv0 = 1.0f / fmaxf(sqrtf(sq0), 1e-12f);
            float inv1 = 1.0f / fmaxf(sqrtf(sq1), 1e-12f);
            #pragma unroll
            for (int nt = 0; nt < 8; nt++) {
                *reinterpret_cast<float2*>(sF + lr0 * SF_STRIDE + nt * 8 + t * 2) =
                    make_float2(acc[nt][0] * inv0, acc[nt][1] * inv0);
                *reinterpret_cast<float2*>(sF + lr1 * SF_STRIDE + nt * 8 + t * 2) =
                    make_float2(acc[nt][2] * inv1, acc[nt][3] * inv1);
            }
        }
        __syncthreads();

        // ---- coalesced writeout: half-warp h writes rows h*8..h*8+7 ----
        #pragma unroll 2
        for (int i = 0; i < 8; i++) {
            int r = h * 8 + i;
            int n = tb + r;
            if (n < N_NODES) {
                float4 v = *reinterpret_cast<const float4*>(sF + r * SF_STRIDE + hl * 4);
                reinterpret_cast<float4*>(outc + (size_t)n * OD)[hl] = v;
                __half2 h0 = __floats2half2_rn(v.x, v.y);
                __half2 h1 = __floats2half2_rn(v.z, v.w);
                reinterpret_cast<uint2*>(phd + (size_t)n * D)[hl] =
                    make_uint2(*reinterpret_cast<unsigned*>(&h0),
                               *reinterpret_cast<unsigned*>(&h1));
            }
        }
        __syncthreads();   // sF/sA reused next tile
    }
}

// ---------------- launch ----------------
extern "C" void kernel_launch(void* const* d_in, const int* in_sizes, int n_in,
                              void* d_out, int out_size) {
    (void)in_sizes; (void)n_in; (void)out_size;
    const int*   cols = (const int*)d_in[1];
    const float* vals = (const float*)d_in[2];
    const float* ue   = (const float*)d_in[3];
    const float* ie   = (const float*)d_in[4];
    float* out = (float*)d_out;

    static int smem_set = 0;
    if (!smem_set) {
        cudaFuncSetAttribute(fused_layer_mma,
                             cudaFuncAttributeMaxDynamicSharedMemorySize, SM_TOTAL);
        smem_set = 1;
    }

    zero_fill_kernel<<<(N_ITEMS + 255) / 256, 256>>>();
    fill2_kernel<<<(E_UI + 255) / 256, 256>>>(cols);
    ego_copy_kernel<<<(N_NODES * (D/4) + 255) / 256, 256>>>(ue, ie, out);

    int nblk = 148 * 4;   // grid-stride, one wave at 4 CTAs/SM
    for (int k = 0; k < 3; k++) {
        float* outc = out + (size_t)64 * (k + 1);
        const float* Ws = (const float*)d_in[5 + 4 * k + 0];
        const float* bs = (const float*)d_in[5 + 4 * k + 1];
        const float* Wp = (const float*)d_in[5 + 4 * k + 2];
        const float* bp = (const float*)d_in[5 + 4 * k + 3];
        fused_layer_mma<<<nblk, 256, SM_TOTAL>>>(cols, vals, outc,
                                                 Ws, bs, Wp, bp, k & 1, NTILES);
    }
}